// round 3
// baseline (speedup 1.0000x reference)
#include <cuda_runtime.h>
#include <cstdint>

#define B_  8
#define C_  128
#define H_  192
#define W_  448
#define ND  49

#define TX  32
#define TY  16
#define KC  8
#define NCHUNK (C_ / KC)
#define NT  256

#define S2_ROW 44                   // logical x in [-4, TX+7] -> idx = x+4
#define S2_CH  ((TY + 6) * S2_ROW)  // 22*44 = 968
#define S2_SIZE (KC * S2_CH)        // 7744 floats per buffer
#define SMEM_BYTES (2 * S2_SIZE * sizeof(float))  // 61952 B

__device__ __forceinline__ uint32_t sptr(const void* p) {
    return (uint32_t)__cvta_generic_to_shared(p);
}
__device__ __forceinline__ void cp16(void* dst, const float* src, bool pred) {
    int bytes = pred ? 16 : 0;
    asm volatile("cp.async.cg.shared.global [%0], [%1], 16, %2;\n"
                 :: "r"(sptr(dst)), "l"(src), "r"(bytes));
}
__device__ __forceinline__ void cp4(void* dst, const float* src, bool pred) {
    int bytes = pred ? 4 : 0;
    asm volatile("cp.async.ca.shared.global [%0], [%1], 4, %2;\n"
                 :: "r"(sptr(dst)), "l"(src), "r"(bytes));
}
__device__ __forceinline__ void cp_commit() {
    asm volatile("cp.async.commit_group;\n" ::: "memory");
}

// Load one channel-chunk of the 'second' halo tile into shared memory.
__device__ __forceinline__ void load_chunk(
    float* __restrict__ s2,
    const float* __restrict__ sbase,
    int c0, int x0, int y0, int tid)
{
    const size_t HW = (size_t)H_ * W_;
    // ---- interior: 8ch x 22 rows x 8 float4 = 1408 units ----
#pragma unroll
    for (int it = 0; it < 6; ++it) {
        int u = tid + it * NT;
        if (it < 5 || u < 1408) {
            int c = u / 176;
            int rem = u - c * 176;
            int row = rem >> 3;
            int q = rem & 7;
            int gy = y0 - 3 + row;
            bool p = (gy >= 0) && (gy < H_);
            int gyc = gy < 0 ? 0 : (gy >= H_ ? H_ - 1 : gy);
            const float* src = sbase + (size_t)(c0 + c) * HW + (size_t)gyc * W_ + x0 + q * 4;
            cp16(s2 + c * S2_CH + row * S2_ROW + 4 + q * 4, src, p);
        }
    }
    // ---- edges: 8ch x 22 rows x 6 scalars = 1056 units ----
#pragma unroll
    for (int it = 0; it < 5; ++it) {
        int u = tid + it * NT;
        if (it < 4 || u < 1056) {
            int c = u / 132;
            int rem = u - c * 132;
            int row = rem / 6;
            int e = rem - row * 6;
            int x = (e < 3) ? (e - 3) : (TX + e - 3);
            int gy = y0 - 3 + row;
            int gx = x0 + x;
            bool p = (gy >= 0) && (gy < H_) && (gx >= 0) && (gx < W_);
            int gyc = gy < 0 ? 0 : (gy >= H_ ? H_ - 1 : gy);
            int gxc = gx < 0 ? 0 : (gx >= W_ ? W_ - 1 : gx);
            const float* src = sbase + (size_t)(c0 + c) * HW + (size_t)gyc * W_ + gxc;
            cp4(s2 + c * S2_CH + row * S2_ROW + (x + 4), src, p);
        }
    }
}

// Accumulate flattened displacements d in [D0, D1) for one channel chunk.
// f comes straight from global via a rolling 2-deep LDG prefetch.
template<int D0, int D1>
__device__ __forceinline__ void accumulate(
    const float* __restrict__ s2,
    const float* __restrict__ fpix,   // fbase + y*W + x (channel stride = HW)
    int c0,
    int tyl, int txl, float (&acc)[25][4])
{
    constexpr int RR0 = D0 / 7;
    constexpr int RR1 = (D1 - 1) / 7 + 1;
    const size_t HW = (size_t)H_ * W_;

    float4 f0 = *(const float4*)(fpix + (size_t)(c0 + 0) * HW);
    float4 f1 = *(const float4*)(fpix + (size_t)(c0 + 1) * HW);

#pragma unroll 1
    for (int c = 0; c < KC; ++c) {
        float4 f = f0;
        f0 = f1;
        int cn = c0 + c + 2;
        if (cn > C_ - 1) cn = C_ - 1;          // clamp (harmless re-read)
        f1 = *(const float4*)(fpix + (size_t)cn * HW);

#pragma unroll
        for (int rr = RR0; rr < RR1; ++rr) {
            const int di0 = (rr * 7 < D0) ? (D0 - rr * 7) : 0;
            const int di1 = (rr * 7 + 7 > D1) ? (D1 - rr * 7) : 7;
            const float* vp = s2 + c * S2_CH + (tyl + rr) * S2_ROW + txl * 4;
            float4 v0 = ((const float4*)vp)[0];
            float4 v1 = ((const float4*)vp)[1];
            float4 v2 = ((const float4*)vp)[2];
            float v[12] = { v0.x, v0.y, v0.z, v0.w,
                            v1.x, v1.y, v1.z, v1.w,
                            v2.x, v2.y, v2.z, v2.w };
#pragma unroll
            for (int di = di0; di < di1; ++di) {
                const int a = rr * 7 + di - D0;
                acc[a][0] += f.x * v[di + 1];
                acc[a][1] += f.y * v[di + 2];
                acc[a][2] += f.z * v[di + 3];
                acc[a][3] += f.w * v[di + 4];
            }
        }
    }
}

template<int D0, int D1>
__device__ __forceinline__ void epilogue(
    float* __restrict__ out, const float (&acc)[25][4],
    int b, int y, int x)
{
    const float invC = 1.0f / (float)C_;
#pragma unroll
    for (int d = D0; d < D1; ++d) {
        const int a = d - D0;
        float4 o;
        o.x = acc[a][0] * invC;
        o.y = acc[a][1] * invC;
        o.z = acc[a][2] * invC;
        o.w = acc[a][3] * invC;
        *(float4*)(out + (((size_t)b * ND + d) * H_ + y) * W_ + x) = o;
    }
}

__global__ void __launch_bounds__(NT, 2)
corr_kernel(const float* __restrict__ first,
            const float* __restrict__ second,
            float* __restrict__ out)
{
    extern __shared__ float smem[];
    const int tid = threadIdx.x;
    const int wg   = tid >> 7;        // warpgroup 0 or 1 (displacement split)
    const int wtid = tid & 127;
    const int bx = blockIdx.x, by = blockIdx.y, b = blockIdx.z;
    const int x0 = bx * TX, y0 = by * TY;
    const int txl = wtid & 7;         // 0..7, owns 4 x-pixels
    const int tyl = wtid >> 3;        // 0..15, one y-row

    const size_t HW = (size_t)H_ * W_;
    const float* fbase = first  + (size_t)b * C_ * HW;
    const float* sbase = second + (size_t)b * C_ * HW;
    const float* fpix  = fbase + (size_t)(y0 + tyl) * W_ + x0 + txl * 4;

    float acc[25][4];
#pragma unroll
    for (int d = 0; d < 25; ++d)
#pragma unroll
        for (int p = 0; p < 4; ++p)
            acc[d][p] = 0.0f;

    load_chunk(smem, sbase, 0, x0, y0, tid);
    cp_commit();

#pragma unroll 1
    for (int k = 0; k < NCHUNK; ++k) {
        if (k < NCHUNK - 1) {
            float* nb = smem + ((k + 1) & 1) * S2_SIZE;
            load_chunk(nb, sbase, (k + 1) * KC, x0, y0, tid);
            cp_commit();
            asm volatile("cp.async.wait_group 1;\n" ::: "memory");
        } else {
            asm volatile("cp.async.wait_group 0;\n" ::: "memory");
        }
        __syncthreads();

        const float* s2 = smem + (k & 1) * S2_SIZE;

        if (wg == 0) accumulate<0, 24>(s2, fpix, k * KC, tyl, txl, acc);
        else         accumulate<24, 49>(s2, fpix, k * KC, tyl, txl, acc);

        __syncthreads();
    }

    const int y = y0 + tyl;
    const int x = x0 + txl * 4;
    if (wg == 0) epilogue<0, 24>(out, acc, b, y, x);
    else         epilogue<24, 49>(out, acc, b, y, x);
}

extern "C" void kernel_launch(void* const* d_in, const int* in_sizes, int n_in,
                              void* d_out, int out_size)
{
    const float* first  = (const float*)d_in[0];
    const float* second = (const float*)d_in[1];
    float* out = (float*)d_out;

    cudaFuncSetAttribute(corr_kernel,
                         cudaFuncAttributeMaxDynamicSharedMemorySize,
                         (int)SMEM_BYTES);

    dim3 grid(W_ / TX, H_ / TY, B_);   // 14 x 12 x 8 = 1344 CTAs
    dim3 block(NT);
    corr_kernel<<<grid, block, SMEM_BYTES>>>(first, second, out);
}